// round 13
// baseline (speedup 1.0000x reference)
#include <cuda_runtime.h>
#include <cuda_fp16.h>
#include <cstdint>

// ---------------------------------------------------------------------------
// MSAttention: einsum 'bkhwlm,bkhwlnf->bkhwlf' factorizes as
// (sum_m A)*(sum_n V) = 1 * sum_n V  =>  attention is dead code. Output is a
// sum of V-projections of (block-sum) pooled inputs:
//   out0 = Wvkid0*pool2(x1) + up4( Wvpeer0*pool4(x0) )
//   out1 = Wvkid1*pool2(x2) + up2( Wvpeer1*pool2(x1) + Wvpar1*x0 )
//   out2 =                    up2( Wvpeer2*pool2(x2) + Wvpar2*x1 )
// Wv* = rows [256,512) of the kv weights.
//
// SINGLE kernel launch. mma.sync m16n8k16 fp16/fp32-acc; operands staged
// chunk-planar + pre-swizzled so each 8KB tile loads with one cp.async.bulk.
// Staging (pool + fp32->fp16) is done cooperatively INSIDE the kernel by the
// 296 wave-1 CTAs: planes 0-2 in the prologue, plane c+3 during mainloop
// iteration c, gated by per-plane completion counters. C-producing CTAs
// signal g_done; consumers wait only before their gather-add epilogue.
// A ticket counter resets all flags at kernel end (graph-replay safe).
// ---------------------------------------------------------------------------

// ---- staged operands ----
__device__ __align__(1024) __half g_P0[128 * 256];
__device__ __align__(1024) __half g_Pa[2048 * 256];
__device__ __align__(1024) __half g_Pb[8192 * 256];
__device__ __align__(1024) __half g_W[7 * 65536];
__device__ float g_C0[128 * 256];
__device__ float g_C1[2048 * 256];
__device__ int g_pcnt[8];
__device__ int g_done;
__device__ int g_fin;

#define PLANE_PAIRS 24320      // 256 (P0) + 4096 (Pa) + 16384 (Pb) + 3584 (W)
#define PREP_CTAS 296
#define SLICE 83               // ceil-ish: 293*83 + 1 = 24320

// ---------------------------------------------------------------------------
// PTX helpers (baseline sm_90 features only; tcgen05 is 'a'-gated, unusable)
// ---------------------------------------------------------------------------
__device__ __forceinline__ uint32_t smem_to_u32(const void* p) {
    uint32_t a;
    asm("{ .reg .u64 t; cvta.to.shared.u64 t, %1; cvt.u32.u64 %0, t; }" : "=r"(a) : "l"(p));
    return a;
}
__device__ __forceinline__ void bulk_cp(uint32_t smem, const void* gmem, uint32_t bytes,
                                        uint32_t mbar) {
    asm volatile(
        "cp.async.bulk.shared::cluster.global.mbarrier::complete_tx::bytes [%0], [%1], %2, [%3];"
        :: "r"(smem), "l"(gmem), "r"(bytes), "r"(mbar) : "memory");
}
#define MBARRIER_INIT(mbar, cnt) \
    asm volatile("mbarrier.init.shared.b64 [%0], %1;" :: "r"((uint32_t)(mbar)), "r"((uint32_t)(cnt)) : "memory")
#define MBARRIER_EXPECT_TX(mbar, tx) \
    asm volatile("mbarrier.arrive.expect_tx.shared.b64 _, [%0], %1;" :: "r"((uint32_t)(mbar)), "r"((uint32_t)(tx)) : "memory")
#define MBARRIER_WAIT_PARITY(mbar, par) do {                                      \
    uint32_t _m = (uint32_t)(mbar); uint32_t _p = (uint32_t)(par); uint32_t _d;   \
    asm volatile("{\n\t.reg .pred p;\n\t"                                         \
        "mbarrier.try_wait.parity.acquire.cta.shared::cta.b64 p, [%1], %2;\n\t"   \
        "selp.b32 %0, 1, 0, p;\n\t}" : "=r"(_d) : "r"(_m), "r"(_p) : "memory");   \
    if (!_d) {                                                                     \
        asm volatile("{\n\t.reg .pred P1;\n\t"                                    \
            "WL_%=:\n\t"                                                          \
            "mbarrier.try_wait.parity.acquire.cta.shared::cta.b64 P1, [%0], %1, 0x989680;\n\t" \
            "@P1 bra.uni WD_%=;\n\t"                                              \
            "bra.uni WL_%=;\n\t"                                                  \
            "WD_%=:\n\t}" :: "r"(_m), "r"(_p) : "memory");                        \
    }                                                                              \
} while (0)

__device__ __forceinline__ void ldsm4(uint32_t* r, uint32_t addr) {
    asm volatile("ldmatrix.sync.aligned.m8n8.x4.shared.b16 {%0,%1,%2,%3}, [%4];"
                 : "=r"(r[0]), "=r"(r[1]), "=r"(r[2]), "=r"(r[3]) : "r"(addr));
}
__device__ __forceinline__ void mma16816(float* d, const uint32_t* a, const uint32_t* b) {
    asm volatile(
        "mma.sync.aligned.m16n8k16.row.col.f32.f16.f16.f32 "
        "{%0,%1,%2,%3}, {%4,%5,%6,%7}, {%8,%9}, {%0,%1,%2,%3};"
        : "+f"(d[0]), "+f"(d[1]), "+f"(d[2]), "+f"(d[3])
        : "r"(a[0]), "r"(a[1]), "r"(a[2]), "r"(a[3]), "r"(b[0]), "r"(b[1]));
}
__device__ __forceinline__ void sts128(uint32_t addr, uint4 v) {
    asm volatile("st.shared.v4.b32 [%0], {%1,%2,%3,%4};"
                 :: "r"(addr), "r"(v.x), "r"(v.y), "r"(v.z), "r"(v.w) : "memory");
}

// slot byte-offset inside a chunk plane for (row r, 16B-slot t)
__device__ __forceinline__ uint32_t plane_off(int r, int t) {
    return (uint32_t)((r >> 1) * 128 + (((((r & 1) << 2) | t) ^ ((r >> 1) & 7)) << 4));
}

__device__ __forceinline__ uint4 pack8(float4 a, float4 b) {
    __half2 h0 = __floats2half2_rn(a.x, a.y);
    __half2 h1 = __floats2half2_rn(a.z, a.w);
    __half2 h2 = __floats2half2_rn(b.x, b.y);
    __half2 h3 = __floats2half2_rn(b.z, b.w);
    uint4 u;
    u.x = *(uint32_t*)&h0; u.y = *(uint32_t*)&h1;
    u.z = *(uint32_t*)&h2; u.w = *(uint32_t*)&h3;
    return u;
}

// ---------------------------------------------------------------------------
// In-kernel staging: one "pair" = 64B channel span (two 16B slots) of one row
// of one chunk plane. Plane-local pair index q in [0, PLANE_PAIRS).
// ---------------------------------------------------------------------------
struct PrepSrc { const float *x0, *x1, *x2; const float* w[7]; };

template <int F>
__device__ __forceinline__ void pool_pair(const float* __restrict__ in, __half* dst,
                                          int R, int Hc, int plane, int r, int tp) {
    int q = r % Hc;
    int tmp = r / Hc;
    int p = tmp % Hc;
    int b = tmp / Hc;
    const int c16 = plane * 8 + tp * 4;
    const int Win = Hc * F;
    const float4* in4 = (const float4*)in;
    float4 s[4];
#pragma unroll
    for (int j = 0; j < 4; ++j) s[j] = make_float4(0.f, 0.f, 0.f, 0.f);
#pragma unroll
    for (int dy = 0; dy < F; ++dy)
#pragma unroll
        for (int dx = 0; dx < F; ++dx) {
            const float4* pp =
                &in4[(size_t)((b * Hc * F + p * F + dy) * Win + q * F + dx) * 64 + c16];
#pragma unroll
            for (int j = 0; j < 4; ++j) {
                float4 v = pp[j];
                s[j].x += v.x; s[j].y += v.y; s[j].z += v.z; s[j].w += v.w;
            }
        }
    __half* base = dst + (size_t)plane * R * 32;
    *(uint4*)(base + (plane_off(r, tp * 2) >> 1)) = pack8(s[0], s[1]);
    *(uint4*)(base + (plane_off(r, tp * 2 + 1) >> 1)) = pack8(s[2], s[3]);
}

__device__ __forceinline__ void do_pair(const PrepSrc& ps, int plane, int q) {
    const int VOFF = 256 * 256;
    if (q < 256) {
        pool_pair<4>(ps.x0, g_P0, 128, 4, plane, q >> 1, q & 1);
    } else if ((q -= 256) < 4096) {
        pool_pair<2>(ps.x1, g_Pa, 2048, 16, plane, q >> 1, q & 1);
    } else if ((q -= 4096) < 16384) {
        pool_pair<2>(ps.x2, g_Pb, 8192, 32, plane, q >> 1, q & 1);
    } else {
        q -= 16384;
        const int mat = q >> 9;
        const int r = (q & 511) >> 1;
        const int tp = q & 1;
        const float4* src = (const float4*)(ps.w[mat] + VOFF + r * 256 + plane * 32 + tp * 16);
        float4 v0 = src[0], v1 = src[1], v2 = src[2], v3 = src[3];
        __half* base = g_W + ((size_t)mat << 16) + (size_t)plane * 256 * 32;
        *(uint4*)(base + (plane_off(r, tp * 2) >> 1)) = pack8(v0, v1);
        *(uint4*)(base + (plane_off(r, tp * 2 + 1) >> 1)) = pack8(v2, v3);
    }
}

// ---------------------------------------------------------------------------
// GEMM: BM=128, BN=128, BK=32, 8 warps, 4-stage bulk-copy mbarrier pipeline.
// K=512 jobs: chunks 8..15 take A from fp32 gmem (A2f) via LDG+swizzled STS.
// mode 0: plain; 1: scatter-up by F; 2: gather-add Cadd[coarse(m)].
// dep 0 none; 1 producer (signal g_done); 2 consumer (wait before epilogue).
// ---------------------------------------------------------------------------
struct TCJob {
    const __half *A1, *W1, *W2;
    const float* A2f;
    float* out;
    const float* Cadd;
    int aplane;   // bytes per A chunk plane (= R*64)
    int tile_end, Hc, Wc, F, mode, dep;
};
struct TCJobs { TCJob j[5]; PrepSrc ps; int njobs; int nprod; };

#define STG 16384                  // stage bytes: A 8KB + B 8KB
#define SMEM_TOTAL (4 * STG)       // 65536
#define GRID_CTAS 322

__global__ void __launch_bounds__(256, 2)
gemm_tc(TCJobs jobs) {
    extern __shared__ char smem[];
    __shared__ __align__(8) unsigned long long mbars[4];
    const uint32_t sb = smem_to_u32(smem);
    const uint32_t mb = smem_to_u32(mbars);
    const int tid = threadIdx.x;
    const int lid = tid & 31;
    const int wid = tid >> 5;
    const int wm = wid >> 2;       // 0..1
    const int wn = wid & 3;        // 0..3

    const int bt = blockIdx.x;
    int ji = 0;
#pragma unroll
    for (int t = 0; t < 4; ++t)
        if (t + 1 < jobs.njobs && bt >= jobs.j[t].tile_end) ji = t + 1;
    const TCJob jb = jobs.j[ji];
    const int local = bt - (ji == 0 ? 0 : jobs.j[ji - 1].tile_end);
    const int m0 = (local >> 1) * 128;
    const int n0 = (local & 1) * 128;

    const int nch = jb.W2 ? 16 : 8;
    const bool prepper = (bt < PREP_CTAS);
    const int plo = bt * SLICE;
    const int phi = min(plo + SLICE, PLANE_PAIRS);
    const int pcnt = max(0, phi - plo);

    if (tid == 0) {
#pragma unroll
        for (int s = 0; s < 4; ++s) MBARRIER_INIT(mb + 8 * s, 1);
    }

    // ---- prologue staging: planes 0..2, all slices in one parallel shot ----
    if (prepper && tid < 3 * SLICE) {
        const int p = tid / SLICE;
        const int q = plo + (tid - p * SLICE);
        if (q < PLANE_PAIRS) do_pair(jobs.ps, p, q);
    }
    __threadfence();
    __syncthreads();
    if (tid == 0 && prepper && pcnt) {
        atomicAdd(&g_pcnt[0], pcnt);
        atomicAdd(&g_pcnt[1], pcnt);
        atomicAdd(&g_pcnt[2], pcnt);
    }

    float acc[4][4][4];
#pragma unroll
    for (int a = 0; a < 4; ++a)
#pragma unroll
        for (int b = 0; b < 4; ++b)
#pragma unroll
            for (int c = 0; c < 4; ++c) acc[a][b][c] = 0.f;

    // issue chunk c into stage c%4 (B always bulk; A bulk only for c<8)
    auto issue = [&](int c) {
        const int s = c & 3;
        const uint32_t stg = sb + s * STG;
        const bool bulkA = (c < 8);
        MBARRIER_EXPECT_TX(mb + 8 * s, bulkA ? 16384u : 8192u);
        const char* wsrc = (const char*)((c < 8) ? jb.W1 : jb.W2) + (c & 7) * 16384 + n0 * 64;
        bulk_cp(stg + 8192, wsrc, 8192, mb + 8 * s);
        if (bulkA) {
            const char* asrc = (const char*)jb.A1 + (size_t)c * jb.aplane + (size_t)m0 * 64;
            bulk_cp(stg, asrc, 8192, mb + 8 * s);
        }
    };
    auto wait_issue = [&](int c) {   // tid==0 only
        const int p = c & 7;
        while (atomicAdd(&g_pcnt[p], 0) < PLANE_PAIRS) { }
        issue(c);
    };

    if (tid == 0) { wait_issue(0); wait_issue(1); wait_issue(2); }

    // A ldmatrix addresses (x4: 16 rows x 16 k)
    const int rA0 = wm * 64 + (lid & 15);
    const int hiA = lid >> 4;
    const uint32_t aBase = (rA0 >> 1) * 128;
    const int xvA = (rA0 >> 1) & 7;
    const int pbA = (rA0 & 1) << 2;
    const uint32_t soA0 = (uint32_t)(((pbA | hiA) ^ xvA) << 4);
    const uint32_t soA1 = (uint32_t)(((pbA | (2 + hiA)) ^ xvA) << 4);

    // B ldmatrix addresses (x4 covering TWO n8 tiles: lanes 16-31 -> rows +8)
    const int rB = wn * 32 + ((lid >> 4) & 1) * 8 + (lid & 7);
    const int hiB = (lid >> 3) & 1;
    const uint32_t bBase = (rB >> 1) * 128;
    const int xvB = (rB >> 1) & 7;
    const int pbB = (rB & 1) << 2;
    const uint32_t soB0 = (uint32_t)(((pbB | hiB) ^ xvB) << 4);
    const uint32_t soB1 = (uint32_t)(((pbB | (2 + hiB)) ^ xvB) << 4);

    // fp32 A path indices (thread covers one row, two 16B slots)
    const int fr = tid >> 1;
    const int ft = (tid & 1) * 2;

    float4 st[4];

#pragma unroll 1
    for (int c = 0; c < nch; ++c) {
        const int s = c & 3;
        MBARRIER_WAIT_PARITY(mb + 8 * s, (c >> 2) & 1);

        const int c3 = c + 3;
        const bool ld2 = (c3 < nch) && (c3 >= 8);
        if (ld2) {
            const float* g = jb.A2f + (size_t)(m0 + fr) * 256 + (c3 & 7) * 32 + ft * 8;
            st[0] = ((const float4*)g)[0];
            st[1] = ((const float4*)g)[1];
            st[2] = ((const float4*)g)[2];
            st[3] = ((const float4*)g)[3];
        }

        const uint32_t sA = sb + s * STG;
        const uint32_t sB = sA + 8192;
#pragma unroll
        for (int ks = 0; ks < 2; ++ks) {
            uint32_t b[4][2];
            const uint32_t so = ks ? soB1 : soB0;
            {
                uint32_t q[4];
                ldsm4(q, sB + bBase + so);          // n-tiles 0,1
                b[0][0] = q[0]; b[0][1] = q[1];
                b[1][0] = q[2]; b[1][1] = q[3];
                ldsm4(q, sB + bBase + 1024 + so);   // n-tiles 2,3 (+16 rows)
                b[2][0] = q[0]; b[2][1] = q[1];
                b[3][0] = q[2]; b[3][1] = q[3];
            }
            const uint32_t sak = ks ? soA1 : soA0;
#pragma unroll
            for (int mi = 0; mi < 4; ++mi) {
                uint32_t a[4];
                ldsm4(a, sA + aBase + mi * 1024 + sak);
#pragma unroll
                for (int ni = 0; ni < 4; ++ni)
                    mma16816(acc[mi][ni], a, b[ni]);
            }
        }

        if (ld2) {
            const uint32_t stg = sb + (c3 & 3) * STG + (fr >> 1) * 128;
            const int pb = (fr & 1) << 2;
            const int xv = (fr >> 1) & 7;
            sts128(stg + (((pb | ft) ^ xv) << 4), pack8(st[0], st[1]));
            sts128(stg + (((pb | (ft + 1)) ^ xv) << 4), pack8(st[2], st[3]));
        }

        // staging for plane c3 (3..7) interleaved with mainloop
        if (c3 >= 3 && c3 <= 7) {
            if (prepper && tid < pcnt) do_pair(jobs.ps, c3, plo + tid);
            __threadfence();
            __syncthreads();
            if (tid == 0 && prepper && pcnt) atomicAdd(&g_pcnt[c3], pcnt);
        } else {
            __syncthreads();
        }
        if (c3 < nch && tid == 0) wait_issue(c3);
    }

    // Consumers: wait for all C producers before the gather-add epilogue.
    if (jb.dep == 2) {
        if (tid == 0) {
            while (atomicAdd(&g_done, 0) < jobs.nprod) { }
        }
        __syncthreads();
    }

    // Epilogue. D frag: lane holds (row g, col 2tg), (row g+8) pairs.
    const int g = lid >> 2;
    const int tg = lid & 3;
#pragma unroll
    for (int mi = 0; mi < 4; ++mi) {
#pragma unroll
        for (int half = 0; half < 2; ++half) {
            const int rm = m0 + wm * 64 + mi * 16 + g + half * 8;
            if (jb.mode == 0) {
                float* dst = jb.out + (size_t)rm * 256;
#pragma unroll
                for (int ni = 0; ni < 4; ++ni) {
                    const int cn = n0 + wn * 32 + ni * 8 + tg * 2;
                    *(float2*)(dst + cn) = make_float2(acc[mi][ni][half * 2],
                                                       acc[mi][ni][half * 2 + 1]);
                }
            } else if (jb.mode == 1) {
                const int HW = jb.Hc * jb.Wc;
                const int b = rm / HW;
                const int rem = rm - b * HW;
                const int h = rem / jb.Wc;
                const int w = rem - h * jb.Wc;
                const int Wf = jb.Wc * jb.F;
                for (int dy = 0; dy < jb.F; ++dy)
                    for (int dx = 0; dx < jb.F; ++dx) {
                        size_t fm = (size_t)(b * jb.Hc * jb.F + h * jb.F + dy) * Wf
                                    + (w * jb.F + dx);
                        float* dst = jb.out + fm * 256;
#pragma unroll
                        for (int ni = 0; ni < 4; ++ni) {
                            const int cn = n0 + wn * 32 + ni * 8 + tg * 2;
                            *(float2*)(dst + cn) = make_float2(acc[mi][ni][half * 2],
                                                               acc[mi][ni][half * 2 + 1]);
                        }
                    }
            } else {
                const int Wf = jb.Wc * jb.F;
                const int HWf = jb.Hc * jb.F * Wf;
                const int b = rm / HWf;
                const int rem = rm - b * HWf;
                const int h = rem / Wf;
                const int w = rem - h * Wf;
                const int crow = (b * jb.Hc + h / jb.F) * jb.Wc + (w / jb.F);
                const float* csrc = jb.Cadd + (size_t)crow * 256;
                float* dst = jb.out + (size_t)rm * 256;
#pragma unroll
                for (int ni = 0; ni < 4; ++ni) {
                    const int cn = n0 + wn * 32 + ni * 8 + tg * 2;
                    float2 cv = *(const float2*)(csrc + cn);
                    *(float2*)(dst + cn) = make_float2(acc[mi][ni][half * 2] + cv.x,
                                                       acc[mi][ni][half * 2 + 1] + cv.y);
                }
            }
        }
    }

    // Producers: make C visible, then signal.
    if (jb.dep == 1) {
        __threadfence();
        __syncthreads();
        if (tid == 0) atomicAdd(&g_done, 1);
    }

    // Kernel-exit ticket: last CTA resets all flags (graph-replay safe).
    __syncthreads();
    if (tid == 0) {
        __threadfence();
        int t = atomicAdd(&g_fin, 1);
        if (t == GRID_CTAS - 1) {
            g_done = 0;
#pragma unroll
            for (int p = 0; p < 8; ++p) g_pcnt[p] = 0;
            __threadfence();
            g_fin = 0;
        }
    }
}

// ---------------------------------------------------------------------------
// Launch
// ---------------------------------------------------------------------------
extern "C" void kernel_launch(void* const* d_in, const int* in_sizes, int n_in,
                              void* d_out, int out_size) {
    (void)n_in; (void)out_size;

    const float* x0 = (const float*)d_in[0];   // [8,16,16,256]
    const float* x1 = (const float*)d_in[1];   // [8,32,32,256]
    const float* x2 = (const float*)d_in[2];   // [8,64,64,256]

    // setup_inputs() builds the dict INTERLEAVED (qpeer_w0, kvpeer_w0, ...).
    const bool inter = (in_sizes[4] == 2 * 256 * 256);
    const float* kvpeer0 = (const float*)d_in[inter ? 4  : 6];
    const float* kvpeer1 = (const float*)d_in[inter ? 6  : 7];
    const float* kvpeer2 = (const float*)d_in[inter ? 8  : 8];
    const float* kvpar1  = (const float*)d_in[inter ? 10 : 11];
    const float* kvpar2  = (const float*)d_in[inter ? 12 : 12];
    const float* kvkid0  = (const float*)d_in[inter ? 14 : 15];
    const float* kvkid1  = (const float*)d_in[inter ? 16 : 16];

    __half *P0, *Pa, *Pb, *W;
    float *C0, *C1;
    cudaGetSymbolAddress((void**)&P0, g_P0);
    cudaGetSymbolAddress((void**)&Pa, g_Pa);
    cudaGetSymbolAddress((void**)&Pb, g_Pb);
    cudaGetSymbolAddress((void**)&W, g_W);
    cudaGetSymbolAddress((void**)&C0, g_C0);
    cudaGetSymbolAddress((void**)&C1, g_C1);

    float* out0 = (float*)d_out;                 // 8*16*16*256
    float* out1 = out0 + 8 * 16 * 16 * 256;      // 8*32*32*256
    float* out2 = out1 + 8 * 32 * 32 * 256;      // 8*64*64*256

    cudaFuncSetAttribute(gemm_tc, cudaFuncAttributeMaxDynamicSharedMemorySize, SMEM_TOTAL);

    __half* W0 = W;             // peer0
    __half* W1 = W + 65536;     // peer1
    __half* W2 = W + 131072;    // peer2
    __half* W3 = W + 196608;    // par1
    __half* W4 = W + 262144;    // par2
    __half* W5 = W + 327680;    // kid0
    __half* W6 = W + 393216;    // kid1

    TCJobs tj;
    tj.njobs = 5;
    tj.nprod = 34;
    tj.ps.x0 = x0; tj.ps.x1 = x1; tj.ps.x2 = x2;
    tj.ps.w[0] = kvpeer0; tj.ps.w[1] = kvpeer1; tj.ps.w[2] = kvpeer2;
    tj.ps.w[3] = kvpar1;  tj.ps.w[4] = kvpar2;  tj.ps.w[5] = kvkid0;  tj.ps.w[6] = kvkid1;
    //        A1  W1  W2      A2f  out   Cadd    aplane    end  Hc  Wc F  mode dep
    tj.j[0] = { P0, W0, nullptr, nullptr, C0,   nullptr, 128 * 64,  2,   0,  0, 0, 0, 1 };
    tj.j[1] = { Pa, W1, W3,      x0,      C1,   nullptr, 2048 * 64, 34,  0,  0, 0, 0, 1 };
    tj.j[2] = { Pb, W2, W4,      x1,      out2, nullptr, 8192 * 64, 162, 32, 32, 2, 1, 0 };
    tj.j[3] = { Pa, W5, nullptr, nullptr, out0, C0,      2048 * 64, 194, 4,  4,  4, 2, 2 };
    tj.j[4] = { Pb, W6, nullptr, nullptr, out1, C1,      8192 * 64, 322, 16, 16, 2, 2, 2 };
    gemm_tc<<<GRID_CTAS, 256, SMEM_TOTAL>>>(tj);
}

// round 14
// speedup vs baseline: 1.7399x; 1.7399x over previous
#include <cuda_runtime.h>
#include <cuda_fp16.h>
#include <cstdint>

// ---------------------------------------------------------------------------
// MSAttention: einsum 'bkhwlm,bkhwlnf->bkhwlf' factorizes as
// (sum_m A)*(sum_n V) = 1 * sum_n V  =>  attention is dead code. Output is a
// sum of V-projections of (block-sum) pooled inputs:
//   out0 = Wvkid0*pool2(x1) + up4( Wvpeer0*pool4(x0) )
//   out1 = Wvkid1*pool2(x2) + up2( Wvpeer1*pool2(x1) + Wvpar1*x0 )
//   out2 =                    up2( Wvpeer2*pool2(x2) + Wvpar2*x1 )
// Wv* = rows [256,512) of the kv weights.
//
// Two launches (in-kernel staging with cross-CTA gating regressed in R13):
//  1) prep: pools + fp32->fp16, chunk-planar pre-swizzled. Pb (the 32MB x2
//     pool) uses a warp-per-row fully-coalesced path; P0/Pa/W keep the
//     proven layout.
//  2) gemm: mma.sync m16n8k16 fp16/fp32-acc, 8KB tiles via cp.async.bulk,
//     4-stage mbarrier pipeline, ONE launch for all 322 tiles. C-producing
//     CTAs signal g_done; consumers wait only before the gather-add epilogue.
// ---------------------------------------------------------------------------

// ---- staged operands ----
__device__ __align__(1024) __half g_P0[128 * 256];
__device__ __align__(1024) __half g_Pa[2048 * 256];
__device__ __align__(1024) __half g_Pb[8192 * 256];
__device__ __align__(1024) __half g_W[7 * 65536];
__device__ float g_C0[128 * 256];
__device__ float g_C1[2048 * 256];
__device__ int g_done;

// ---------------------------------------------------------------------------
// PTX helpers (baseline sm_90 features only; tcgen05 is 'a'-gated, unusable)
// ---------------------------------------------------------------------------
__device__ __forceinline__ uint32_t smem_to_u32(const void* p) {
    uint32_t a;
    asm("{ .reg .u64 t; cvta.to.shared.u64 t, %1; cvt.u32.u64 %0, t; }" : "=r"(a) : "l"(p));
    return a;
}
__device__ __forceinline__ void bulk_cp(uint32_t smem, const void* gmem, uint32_t bytes,
                                        uint32_t mbar) {
    asm volatile(
        "cp.async.bulk.shared::cluster.global.mbarrier::complete_tx::bytes [%0], [%1], %2, [%3];"
        :: "r"(smem), "l"(gmem), "r"(bytes), "r"(mbar) : "memory");
}
#define MBARRIER_INIT(mbar, cnt) \
    asm volatile("mbarrier.init.shared.b64 [%0], %1;" :: "r"((uint32_t)(mbar)), "r"((uint32_t)(cnt)) : "memory")
#define MBARRIER_EXPECT_TX(mbar, tx) \
    asm volatile("mbarrier.arrive.expect_tx.shared.b64 _, [%0], %1;" :: "r"((uint32_t)(mbar)), "r"((uint32_t)(tx)) : "memory")
#define MBARRIER_WAIT_PARITY(mbar, par) do {                                      \
    uint32_t _m = (uint32_t)(mbar); uint32_t _p = (uint32_t)(par); uint32_t _d;   \
    asm volatile("{\n\t.reg .pred p;\n\t"                                         \
        "mbarrier.try_wait.parity.acquire.cta.shared::cta.b64 p, [%1], %2;\n\t"   \
        "selp.b32 %0, 1, 0, p;\n\t}" : "=r"(_d) : "r"(_m), "r"(_p) : "memory");   \
    if (!_d) {                                                                     \
        asm volatile("{\n\t.reg .pred P1;\n\t"                                    \
            "WL_%=:\n\t"                                                          \
            "mbarrier.try_wait.parity.acquire.cta.shared::cta.b64 P1, [%0], %1, 0x989680;\n\t" \
            "@P1 bra.uni WD_%=;\n\t"                                              \
            "bra.uni WL_%=;\n\t"                                                  \
            "WD_%=:\n\t}" :: "r"(_m), "r"(_p) : "memory");                        \
    }                                                                              \
} while (0)

__device__ __forceinline__ void ldsm4(uint32_t* r, uint32_t addr) {
    asm volatile("ldmatrix.sync.aligned.m8n8.x4.shared.b16 {%0,%1,%2,%3}, [%4];"
                 : "=r"(r[0]), "=r"(r[1]), "=r"(r[2]), "=r"(r[3]) : "r"(addr));
}
__device__ __forceinline__ void mma16816(float* d, const uint32_t* a, const uint32_t* b) {
    asm volatile(
        "mma.sync.aligned.m16n8k16.row.col.f32.f16.f16.f32 "
        "{%0,%1,%2,%3}, {%4,%5,%6,%7}, {%8,%9}, {%0,%1,%2,%3};"
        : "+f"(d[0]), "+f"(d[1]), "+f"(d[2]), "+f"(d[3])
        : "r"(a[0]), "r"(a[1]), "r"(a[2]), "r"(a[3]), "r"(b[0]), "r"(b[1]));
}
__device__ __forceinline__ void sts128(uint32_t addr, uint4 v) {
    asm volatile("st.shared.v4.b32 [%0], {%1,%2,%3,%4};"
                 :: "r"(addr), "r"(v.x), "r"(v.y), "r"(v.z), "r"(v.w) : "memory");
}

// slot byte-offset inside a chunk plane for (row r, 16B-slot t)
__device__ __forceinline__ uint32_t plane_off(int r, int t) {
    return (uint32_t)((r >> 1) * 128 + (((((r & 1) << 2) | t) ^ ((r >> 1) & 7)) << 4));
}

__device__ __forceinline__ uint4 pack8(float4 a, float4 b) {
    __half2 h0 = __floats2half2_rn(a.x, a.y);
    __half2 h1 = __floats2half2_rn(a.z, a.w);
    __half2 h2 = __floats2half2_rn(b.x, b.y);
    __half2 h3 = __floats2half2_rn(b.z, b.w);
    uint4 u;
    u.x = *(uint32_t*)&h0; u.y = *(uint32_t*)&h1;
    u.z = *(uint32_t*)&h2; u.w = *(uint32_t*)&h3;
    return u;
}

// ---------------------------------------------------------------------------
// Prep: pools + fp32->fp16, written chunk-planar pre-swizzled.
// Blocks [0, 496):   P0 / Pa / weights (proven slot-per-thread layout).
// Blocks [496,1520): Pb via warp-per-row, fully-coalesced 512B loads.
// ---------------------------------------------------------------------------
#define S0 (128 * 32)      // P0 slots
#define S1 (2048 * 32)     // Pa
#define SW (7 * 256 * 32)  // weights
#define NPQ (S0 + S1 + SW) // 126976 = 496 * 256
#define PREP_BLK1 496
#define PB_BLOCKS 1024
#define PREP_BLOCKS (PREP_BLK1 + PB_BLOCKS)

struct PrepArgs {
    const float* x0; const float* x1; const float* x2;
    const float* w[7];
};

__device__ __forceinline__ float4 pool4f(const float* in, int i, int Hc, int f) {
    int Wc = Hc;
    int c4 = i & 63;
    int r = i >> 6;
    int q = r % Wc; r /= Wc;
    int p = r % Hc;
    int b = r / Hc;
    int Win = Wc * f;
    const float4* in4 = (const float4*)in;
    float4 s = make_float4(0.f, 0.f, 0.f, 0.f);
    for (int dy = 0; dy < f; ++dy)
        for (int dx = 0; dx < f; ++dx) {
            float4 v = in4[(size_t)((b * Hc * f + p * f + dy) * Win + q * f + dx) * 64 + c4];
            s.x += v.x; s.y += v.y; s.z += v.z; s.w += v.w;
        }
    return s;
}

__device__ __forceinline__ void prep_pool(const float* in, __half* dst, int R, int Hc,
                                          int f, int i) {
    const int t = i & 3;
    const int r = (i >> 2) % R;
    const int c = (i >> 2) / R;
    const int c4 = c * 8 + t * 2;
    float4 v0 = pool4f(in, r * 64 + c4, Hc, f);
    float4 v1 = pool4f(in, r * 64 + c4 + 1, Hc, f);
    __half* p = dst + (size_t)c * R * 32 + (plane_off(r, t) >> 1);
    *(uint4*)p = pack8(v0, v1);
}

__device__ __forceinline__ void pb_store(int r, int j, float4 v) {
    const int pl = j >> 3;
    const int t = (j >> 1) & 3;
    const int hf = j & 1;
    char* dst = (char*)g_Pb + (size_t)pl * 524288 + plane_off(r, t) + hf * 8;
    __half2 h0 = __floats2half2_rn(v.x, v.y);
    __half2 h1 = __floats2half2_rn(v.z, v.w);
    uint2 u;
    u.x = *(uint32_t*)&h0; u.y = *(uint32_t*)&h1;
    *(uint2*)dst = u;
}

__global__ void prep_kernel(PrepArgs pa) {
    const int tid = threadIdx.x;
    if (blockIdx.x == 0 && tid == 0) g_done = 0;
    const int VOFF = 256 * 256;

    if (blockIdx.x < PREP_BLK1) {
        int i = blockIdx.x * 256 + tid;
        if (i < S0) {
            prep_pool(pa.x0, g_P0, 128, 4, 4, i);
        } else if ((i -= S0) < S1) {
            prep_pool(pa.x1, g_Pa, 2048, 16, 2, i);
        } else {
            i -= S1;
            const int mat = i >> 13;          // 256*32 slots per matrix
            const int rem = i & 8191;
            const int c = rem >> 10;
            const int r = (rem >> 2) & 255;
            const int t = rem & 3;
            const float* src = pa.w[mat] + VOFF + r * 256 + c * 32 + t * 8;
            float4 v0 = ((const float4*)src)[0];
            float4 v1 = ((const float4*)src)[1];
            __half* p = g_W + ((size_t)mat << 16) + (size_t)c * 256 * 32 + (plane_off(r, t) >> 1);
            *(uint4*)p = pack8(v0, v1);
        }
    } else {
        // Pb: warp-per-output-row, fully coalesced 512B warp loads.
        const int w = (blockIdx.x - PREP_BLK1) * 8 + (tid >> 5);   // row 0..8191
        const int lane = tid & 31;
        const int b = w >> 10;
        const int rem = w & 1023;
        const int p = rem >> 5;
        const int q = rem & 31;
        const float4* x2v = (const float4*)pa.x2;
        const size_t base = ((size_t)(b * 64 + 2 * p) * 64 + 2 * q) * 64;
        const float4* s00 = x2v + base;            // (2p,   2q)
        const float4* s01 = x2v + base + 64;       // (2p,   2q+1)
        const float4* s10 = x2v + base + 4096;     // (2p+1, 2q)
        const float4* s11 = x2v + base + 4096 + 64;
        float4 a0 = s00[lane], a1 = s01[lane], a2 = s10[lane], a3 = s11[lane];
        float4 b0 = s00[lane + 32], b1 = s01[lane + 32], b2 = s10[lane + 32], b3 = s11[lane + 32];
        float4 v0 = make_float4(a0.x + a1.x + a2.x + a3.x, a0.y + a1.y + a2.y + a3.y,
                                a0.z + a1.z + a2.z + a3.z, a0.w + a1.w + a2.w + a3.w);
        float4 v1 = make_float4(b0.x + b1.x + b2.x + b3.x, b0.y + b1.y + b2.y + b3.y,
                                b0.z + b1.z + b2.z + b3.z, b0.w + b1.w + b2.w + b3.w);
        pb_store(w, lane, v0);
        pb_store(w, lane + 32, v1);
    }
}

// ---------------------------------------------------------------------------
// GEMM: BM=128, BN=128, BK=32, 8 warps, 4-stage bulk-copy mbarrier pipeline.
// K=512 jobs: chunks 8..15 take A from fp32 gmem (A2f) via LDG+swizzled STS.
// mode 0: plain; 1: scatter-up by F; 2: gather-add Cadd[coarse(m)].
// dep 0 none; 1 producer (signal g_done); 2 consumer (wait before epilogue).
// ---------------------------------------------------------------------------
struct TCJob {
    const __half *A1, *W1, *W2;
    const float* A2f;
    float* out;
    const float* Cadd;
    int aplane;   // bytes per A chunk plane (= R*64)
    int tile_end, Hc, Wc, F, mode, dep;
};
struct TCJobs { TCJob j[5]; int njobs; int nprod; };

#define STG 16384                  // stage bytes: A 8KB + B 8KB
#define SMEM_TOTAL (4 * STG)       // 65536

__global__ void __launch_bounds__(256, 2)
gemm_tc(TCJobs jobs) {
    extern __shared__ char smem[];
    __shared__ __align__(8) unsigned long long mbars[4];
    const uint32_t sb = smem_to_u32(smem);
    const uint32_t mb = smem_to_u32(mbars);
    const int tid = threadIdx.x;
    const int lid = tid & 31;
    const int wid = tid >> 5;
    const int wm = wid >> 2;       // 0..1
    const int wn = wid & 3;        // 0..3

    const int bt = blockIdx.x;
    int ji = 0;
#pragma unroll
    for (int t = 0; t < 4; ++t)
        if (t + 1 < jobs.njobs && bt >= jobs.j[t].tile_end) ji = t + 1;
    const TCJob jb = jobs.j[ji];
    const int local = bt - (ji == 0 ? 0 : jobs.j[ji - 1].tile_end);
    const int m0 = (local >> 1) * 128;
    const int n0 = (local & 1) * 128;

    const int nch = jb.W2 ? 16 : 8;

    float acc[4][4][4];
#pragma unroll
    for (int a = 0; a < 4; ++a)
#pragma unroll
        for (int b = 0; b < 4; ++b)
#pragma unroll
            for (int c = 0; c < 4; ++c) acc[a][b][c] = 0.f;

    if (tid == 0) {
#pragma unroll
        for (int s = 0; s < 4; ++s) MBARRIER_INIT(mb + 8 * s, 1);
    }
    __syncthreads();

    // issue chunk c into stage c%4 (B always bulk; A bulk only for c<8)
    auto issue = [&](int c) {
        const int s = c & 3;
        const uint32_t stg = sb + s * STG;
        const bool bulkA = (c < 8);
        MBARRIER_EXPECT_TX(mb + 8 * s, bulkA ? 16384u : 8192u);
        const char* wsrc = (const char*)((c < 8) ? jb.W1 : jb.W2) + (c & 7) * 16384 + n0 * 64;
        bulk_cp(stg + 8192, wsrc, 8192, mb + 8 * s);
        if (bulkA) {
            const char* asrc = (const char*)jb.A1 + (size_t)c * jb.aplane + (size_t)m0 * 64;
            bulk_cp(stg, asrc, 8192, mb + 8 * s);
        }
    };

    if (tid == 0) { issue(0); issue(1); issue(2); }

    // A ldmatrix addresses (x4: 16 rows x 16 k)
    const int rA0 = wm * 64 + (lid & 15);
    const int hiA = lid >> 4;
    const uint32_t aBase = (rA0 >> 1) * 128;
    const int xvA = (rA0 >> 1) & 7;
    const int pbA = (rA0 & 1) << 2;
    const uint32_t soA0 = (uint32_t)(((pbA | hiA) ^ xvA) << 4);
    const uint32_t soA1 = (uint32_t)(((pbA | (2 + hiA)) ^ xvA) << 4);

    // B ldmatrix addresses (x4 covering TWO n8 tiles: lanes 16-31 -> rows +8)
    const int rB = wn * 32 + ((lid >> 4) & 1) * 8 + (lid & 7);
    const int hiB = (lid >> 3) & 1;
    const uint32_t bBase = (rB >> 1) * 128;
    const int xvB = (rB >> 1) & 7;
    const int pbB = (rB & 1) << 2;
    const uint32_t soB0 = (uint32_t)(((pbB | hiB) ^ xvB) << 4);
    const uint32_t soB1 = (uint32_t)(((pbB | (2 + hiB)) ^ xvB) << 4);

    // fp32 A path indices (thread covers one row, two 16B slots)
    const int fr = tid >> 1;
    const int ft = (tid & 1) * 2;

    float4 st[4];

#pragma unroll 1
    for (int c = 0; c < nch; ++c) {
        const int s = c & 3;
        MBARRIER_WAIT_PARITY(mb + 8 * s, (c >> 2) & 1);

        const int c3 = c + 3;
        const bool ld2 = (c3 < nch) && (c3 >= 8);
        if (ld2) {
            const float* g = jb.A2f + (size_t)(m0 + fr) * 256 + (c3 & 7) * 32 + ft * 8;
            st[0] = ((const float4*)g)[0];
            st[1] = ((const float4*)g)[1];
            st[2] = ((const float4*)g)[2];
            st[3] = ((const float4*)g)[3];
        }

        const uint32_t sA = sb + s * STG;
        const uint32_t sB = sA + 8192;
#pragma unroll
        for (int ks = 0; ks < 2; ++ks) {
            uint32_t b[4][2];
            const uint32_t so = ks ? soB1 : soB0;
            {
                uint32_t q[4];
                ldsm4(q, sB + bBase + so);          // n-tiles 0,1
                b[0][0] = q[0]; b[0][1] = q[1];
                b[1][0] = q[2]; b[1][1] = q[3];
                ldsm4(q, sB + bBase + 1024 + so);   // n-tiles 2,3 (+16 rows)
                b[2][0] = q[0]; b[2][1] = q[1];
                b[3][0] = q[2]; b[3][1] = q[3];
            }
            const uint32_t sak = ks ? soA1 : soA0;
#pragma unroll
            for (int mi = 0; mi < 4; ++mi) {
                uint32_t a[4];
                ldsm4(a, sA + aBase + mi * 1024 + sak);
#pragma unroll
                for (int ni = 0; ni < 4; ++ni)
                    mma16816(acc[mi][ni], a, b[ni]);
            }
        }

        if (ld2) {
            const uint32_t stg = sb + (c3 & 3) * STG + (fr >> 1) * 128;
            const int pb = (fr & 1) << 2;
            const int xv = (fr >> 1) & 7;
            sts128(stg + (((pb | ft) ^ xv) << 4), pack8(st[0], st[1]));
            sts128(stg + (((pb | (ft + 1)) ^ xv) << 4), pack8(st[2], st[3]));
        }
        __syncthreads();
        if (c3 < nch && tid == 0) issue(c3);
    }

    // Consumers: wait for all C producers before the gather-add epilogue.
    if (jb.dep == 2) {
        if (tid == 0) {
            while (atomicAdd(&g_done, 0) < jobs.nprod) { }
        }
        __syncthreads();
    }

    // Epilogue. D frag: lane holds (row g, col 2tg), (row g+8) pairs.
    const int g = lid >> 2;
    const int tg = lid & 3;
#pragma unroll
    for (int mi = 0; mi < 4; ++mi) {
#pragma unroll
        for (int half = 0; half < 2; ++half) {
            const int rm = m0 + wm * 64 + mi * 16 + g + half * 8;
            if (jb.mode == 0) {
                float* dst = jb.out + (size_t)rm * 256;
#pragma unroll
                for (int ni = 0; ni < 4; ++ni) {
                    const int cn = n0 + wn * 32 + ni * 8 + tg * 2;
                    *(float2*)(dst + cn) = make_float2(acc[mi][ni][half * 2],
                                                       acc[mi][ni][half * 2 + 1]);
                }
            } else if (jb.mode == 1) {
                const int HW = jb.Hc * jb.Wc;
                const int b = rm / HW;
                const int rem = rm - b * HW;
                const int h = rem / jb.Wc;
                const int w = rem - h * jb.Wc;
                const int Wf = jb.Wc * jb.F;
                for (int dy = 0; dy < jb.F; ++dy)
                    for (int dx = 0; dx < jb.F; ++dx) {
                        size_t fm = (size_t)(b * jb.Hc * jb.F + h * jb.F + dy) * Wf
                                    + (w * jb.F + dx);
                        float* dst = jb.out + fm * 256;
#pragma unroll
                        for (int ni = 0; ni < 4; ++ni) {
                            const int cn = n0 + wn * 32 + ni * 8 + tg * 2;
                            *(float2*)(dst + cn) = make_float2(acc[mi][ni][half * 2],
                                                               acc[mi][ni][half * 2 + 1]);
                        }
                    }
            } else {
                const int Wf = jb.Wc * jb.F;
                const int HWf = jb.Hc * jb.F * Wf;
                const int b = rm / HWf;
                const int rem = rm - b * HWf;
                const int h = rem / Wf;
                const int w = rem - h * Wf;
                const int crow = (b * jb.Hc + h / jb.F) * jb.Wc + (w / jb.F);
                const float* csrc = jb.Cadd + (size_t)crow * 256;
                float* dst = jb.out + (size_t)rm * 256;
#pragma unroll
                for (int ni = 0; ni < 4; ++ni) {
                    const int cn = n0 + wn * 32 + ni * 8 + tg * 2;
                    float2 cv = *(const float2*)(csrc + cn);
                    *(float2*)(dst + cn) = make_float2(acc[mi][ni][half * 2] + cv.x,
                                                       acc[mi][ni][half * 2 + 1] + cv.y);
                }
            }
        }
    }

    // Producers: make C visible, then signal.
    if (jb.dep == 1) {
        __threadfence();
        __syncthreads();
        if (tid == 0) atomicAdd(&g_done, 1);
    }
}

// ---------------------------------------------------------------------------
// Launch
// ---------------------------------------------------------------------------
extern "C" void kernel_launch(void* const* d_in, const int* in_sizes, int n_in,
                              void* d_out, int out_size) {
    (void)n_in; (void)out_size;

    const float* x0 = (const float*)d_in[0];   // [8,16,16,256]
    const float* x1 = (const float*)d_in[1];   // [8,32,32,256]
    const float* x2 = (const float*)d_in[2];   // [8,64,64,256]

    // setup_inputs() builds the dict INTERLEAVED (qpeer_w0, kvpeer_w0, ...).
    const bool inter = (in_sizes[4] == 2 * 256 * 256);
    const float* kvpeer0 = (const float*)d_in[inter ? 4  : 6];
    const float* kvpeer1 = (const float*)d_in[inter ? 6  : 7];
    const float* kvpeer2 = (const float*)d_in[inter ? 8  : 8];
    const float* kvpar1  = (const float*)d_in[inter ? 10 : 11];
    const float* kvpar2  = (const float*)d_in[inter ? 12 : 12];
    const float* kvkid0  = (const float*)d_in[inter ? 14 : 15];
    const float* kvkid1  = (const float*)d_in[inter ? 16 : 16];

    __half *P0, *Pa, *Pb, *W;
    float *C0, *C1;
    cudaGetSymbolAddress((void**)&P0, g_P0);
    cudaGetSymbolAddress((void**)&Pa, g_Pa);
    cudaGetSymbolAddress((void**)&Pb, g_Pb);
    cudaGetSymbolAddress((void**)&W, g_W);
    cudaGetSymbolAddress((void**)&C0, g_C0);
    cudaGetSymbolAddress((void**)&C1, g_C1);

    float* out0 = (float*)d_out;                 // 8*16*16*256
    float* out1 = out0 + 8 * 16 * 16 * 256;      // 8*32*32*256
    float* out2 = out1 + 8 * 32 * 32 * 256;      // 8*64*64*256

    cudaFuncSetAttribute(gemm_tc, cudaFuncAttributeMaxDynamicSharedMemorySize, SMEM_TOTAL);

    // 1) prep (also resets g_done)
    PrepArgs pa;
    pa.x0 = x0; pa.x1 = x1; pa.x2 = x2;
    pa.w[0] = kvpeer0; pa.w[1] = kvpeer1; pa.w[2] = kvpeer2;
    pa.w[3] = kvpar1;  pa.w[4] = kvpar2;  pa.w[5] = kvkid0;  pa.w[6] = kvkid1;
    prep_kernel<<<PREP_BLOCKS, 256>>>(pa);

    __half* W0 = W;             // peer0
    __half* W1 = W + 65536;     // peer1
    __half* W2 = W + 131072;    // peer2
    __half* W3 = W + 196608;    // par1
    __half* W4 = W + 262144;    // par2
    __half* W5 = W + 327680;    // kid0
    __half* W6 = W + 393216;    // kid1

    // 2) single merged GEMM launch (producers first: blocks 0..33)
    TCJobs tj;
    tj.njobs = 5;
    tj.nprod = 34;
    //        A1  W1  W2      A2f  out   Cadd    aplane    end  Hc  Wc F  mode dep
    tj.j[0] = { P0, W0, nullptr, nullptr, C0,   nullptr, 128 * 64,  2,   0,  0, 0, 0, 1 };
    tj.j[1] = { Pa, W1, W3,      x0,      C1,   nullptr, 2048 * 64, 34,  0,  0, 0, 0, 1 };
    tj.j[2] = { Pb, W2, W4,      x1,      out2, nullptr, 8192 * 64, 162, 32, 32, 2, 1, 0 };
    tj.j[3] = { Pa, W5, nullptr, nullptr, out0, C0,      2048 * 64, 194, 4,  4,  4, 2, 2 };
    tj.j[4] = { Pb, W6, nullptr, nullptr, out1, C1,      8192 * 64, 322, 16, 16, 2, 2, 2 };
    gemm_tc<<<322, 256, SMEM_TOTAL>>>(tj);
}

// round 16
// speedup vs baseline: 1.8051x; 1.0375x over previous
#include <cuda_runtime.h>
#include <cuda_fp16.h>
#include <cstdint>

// ---------------------------------------------------------------------------
// MSAttention: einsum 'bkhwlm,bkhwlnf->bkhwlf' factorizes as
// (sum_m A)*(sum_n V) = 1 * sum_n V  =>  attention is dead code. Output is a
// sum of V-projections of (block-sum) pooled inputs:
//   out0 = Wvkid0*pool2(x1) + up4( Wvpeer0*pool4(x0) )
//   out1 = Wvkid1*pool2(x2) + up2( Wvpeer1*pool2(x1) + Wvpar1*x0 )
//   out2 =                    up2( Wvpeer2*pool2(x2) + Wvpar2*x1 )
// Wv* = rows [256,512) of the kv weights.
//
// prep: pools + fp32->fp16, chunk-planar pre-swizzled (Pb warp-per-row).
// gemm: mma.sync m16n8k16 fp16/fp32-acc, BK=64 chunks (two 32-k planes per
// chunk, 4 bulk copies, 3-stage 96KB ring) -> half the barrier overhead of
// the BK=32 version. ONE launch for all 322 tiles; C-producing CTAs signal
// g_done; consumers wait only before the gather-add epilogue.
// R15 bug fixed: fp32-A plane-1 load is fg[8..11] (k base+32), not fg[4..7].
// ---------------------------------------------------------------------------

// ---- staged operands ----
__device__ __align__(1024) __half g_P0[128 * 256];
__device__ __align__(1024) __half g_Pa[2048 * 256];
__device__ __align__(1024) __half g_Pb[8192 * 256];
__device__ __align__(1024) __half g_W[7 * 65536];
__device__ float g_C0[128 * 256];
__device__ float g_C1[2048 * 256];
__device__ int g_done;

// ---------------------------------------------------------------------------
// PTX helpers (baseline sm_90 features only; tcgen05 is 'a'-gated, unusable)
// ---------------------------------------------------------------------------
__device__ __forceinline__ uint32_t smem_to_u32(const void* p) {
    uint32_t a;
    asm("{ .reg .u64 t; cvta.to.shared.u64 t, %1; cvt.u32.u64 %0, t; }" : "=r"(a) : "l"(p));
    return a;
}
__device__ __forceinline__ void bulk_cp(uint32_t smem, const void* gmem, uint32_t bytes,
                                        uint32_t mbar) {
    asm volatile(
        "cp.async.bulk.shared::cluster.global.mbarrier::complete_tx::bytes [%0], [%1], %2, [%3];"
        :: "r"(smem), "l"(gmem), "r"(bytes), "r"(mbar) : "memory");
}
#define MBARRIER_INIT(mbar, cnt) \
    asm volatile("mbarrier.init.shared.b64 [%0], %1;" :: "r"((uint32_t)(mbar)), "r"((uint32_t)(cnt)) : "memory")
#define MBARRIER_EXPECT_TX(mbar, tx) \
    asm volatile("mbarrier.arrive.expect_tx.shared.b64 _, [%0], %1;" :: "r"((uint32_t)(mbar)), "r"((uint32_t)(tx)) : "memory")
#define MBARRIER_WAIT_PARITY(mbar, par) do {                                      \
    uint32_t _m = (uint32_t)(mbar); uint32_t _p = (uint32_t)(par); uint32_t _d;   \
    asm volatile("{\n\t.reg .pred p;\n\t"                                         \
        "mbarrier.try_wait.parity.acquire.cta.shared::cta.b64 p, [%1], %2;\n\t"   \
        "selp.b32 %0, 1, 0, p;\n\t}" : "=r"(_d) : "r"(_m), "r"(_p) : "memory");   \
    if (!_d) {                                                                     \
        asm volatile("{\n\t.reg .pred P1;\n\t"                                    \
            "WL_%=:\n\t"                                                          \
            "mbarrier.try_wait.parity.acquire.cta.shared::cta.b64 P1, [%0], %1, 0x989680;\n\t" \
            "@P1 bra.uni WD_%=;\n\t"                                              \
            "bra.uni WL_%=;\n\t"                                                  \
            "WD_%=:\n\t}" :: "r"(_m), "r"(_p) : "memory");                        \
    }                                                                              \
} while (0)

__device__ __forceinline__ void ldsm4(uint32_t* r, uint32_t addr) {
    asm volatile("ldmatrix.sync.aligned.m8n8.x4.shared.b16 {%0,%1,%2,%3}, [%4];"
                 : "=r"(r[0]), "=r"(r[1]), "=r"(r[2]), "=r"(r[3]) : "r"(addr));
}
__device__ __forceinline__ void mma16816(float* d, const uint32_t* a, const uint32_t* b) {
    asm volatile(
        "mma.sync.aligned.m16n8k16.row.col.f32.f16.f16.f32 "
        "{%0,%1,%2,%3}, {%4,%5,%6,%7}, {%8,%9}, {%0,%1,%2,%3};"
        : "+f"(d[0]), "+f"(d[1]), "+f"(d[2]), "+f"(d[3])
        : "r"(a[0]), "r"(a[1]), "r"(a[2]), "r"(a[3]), "r"(b[0]), "r"(b[1]));
}
__device__ __forceinline__ void sts128(uint32_t addr, uint4 v) {
    asm volatile("st.shared.v4.b32 [%0], {%1,%2,%3,%4};"
                 :: "r"(addr), "r"(v.x), "r"(v.y), "r"(v.z), "r"(v.w) : "memory");
}

// slot byte-offset inside a chunk plane for (row r, 16B-slot t)
__device__ __forceinline__ uint32_t plane_off(int r, int t) {
    return (uint32_t)((r >> 1) * 128 + (((((r & 1) << 2) | t) ^ ((r >> 1) & 7)) << 4));
}

__device__ __forceinline__ uint4 pack8(float4 a, float4 b) {
    __half2 h0 = __floats2half2_rn(a.x, a.y);
    __half2 h1 = __floats2half2_rn(a.z, a.w);
    __half2 h2 = __floats2half2_rn(b.x, b.y);
    __half2 h3 = __floats2half2_rn(b.z, b.w);
    uint4 u;
    u.x = *(uint32_t*)&h0; u.y = *(uint32_t*)&h1;
    u.z = *(uint32_t*)&h2; u.w = *(uint32_t*)&h3;
    return u;
}

// ---------------------------------------------------------------------------
// Prep: pools + fp32->fp16, written chunk-planar pre-swizzled.
// Blocks [0, 496):   P0 / Pa / weights (slot-per-thread layout).
// Blocks [496,1520): Pb via warp-per-row, fully-coalesced 512B loads.
// ---------------------------------------------------------------------------
#define S0 (128 * 32)      // P0 slots
#define S1 (2048 * 32)     // Pa
#define SW (7 * 256 * 32)  // weights
#define PREP_BLK1 496
#define PB_BLOCKS 1024
#define PREP_BLOCKS (PREP_BLK1 + PB_BLOCKS)

struct PrepArgs {
    const float* x0; const float* x1; const float* x2;
    const float* w[7];
};

__device__ __forceinline__ float4 pool4f(const float* in, int i, int Hc, int f) {
    int Wc = Hc;
    int c4 = i & 63;
    int r = i >> 6;
    int q = r % Wc; r /= Wc;
    int p = r % Hc;
    int b = r / Hc;
    int Win = Wc * f;
    const float4* in4 = (const float4*)in;
    float4 s = make_float4(0.f, 0.f, 0.f, 0.f);
    for (int dy = 0; dy < f; ++dy)
        for (int dx = 0; dx < f; ++dx) {
            float4 v = in4[(size_t)((b * Hc * f + p * f + dy) * Win + q * f + dx) * 64 + c4];
            s.x += v.x; s.y += v.y; s.z += v.z; s.w += v.w;
        }
    return s;
}

__device__ __forceinline__ void prep_pool(const float* in, __half* dst, int R, int Hc,
                                          int f, int i) {
    const int t = i & 3;
    const int r = (i >> 2) % R;
    const int c = (i >> 2) / R;
    const int c4 = c * 8 + t * 2;
    float4 v0 = pool4f(in, r * 64 + c4, Hc, f);
    float4 v1 = pool4f(in, r * 64 + c4 + 1, Hc, f);
    __half* p = dst + (size_t)c * R * 32 + (plane_off(r, t) >> 1);
    *(uint4*)p = pack8(v0, v1);
}

__device__ __forceinline__ void pb_store(int r, int j, float4 v) {
    const int pl = j >> 3;
    const int t = (j >> 1) & 3;
    const int hf = j & 1;
    char* dst = (char*)g_Pb + (size_t)pl * 524288 + plane_off(r, t) + hf * 8;
    __half2 h0 = __floats2half2_rn(v.x, v.y);
    __half2 h1 = __floats2half2_rn(v.z, v.w);
    uint2 u;
    u.x = *(uint32_t*)&h0; u.y = *(uint32_t*)&h1;
    *(uint2*)dst = u;
}

__global__ void prep_kernel(PrepArgs pa) {
    const int tid = threadIdx.x;
    if (blockIdx.x == 0 && tid == 0) g_done = 0;
    const int VOFF = 256 * 256;

    if (blockIdx.x < PREP_BLK1) {
        int i = blockIdx.x * 256 + tid;
        if (i < S0) {
            prep_pool(pa.x0, g_P0, 128, 4, 4, i);
        } else if ((i -= S0) < S1) {
            prep_pool(pa.x1, g_Pa, 2048, 16, 2, i);
        } else {
            i -= S1;
            const int mat = i >> 13;
            const int rem = i & 8191;
            const int c = rem >> 10;
            const int r = (rem >> 2) & 255;
            const int t = rem & 3;
            const float* src = pa.w[mat] + VOFF + r * 256 + c * 32 + t * 8;
            float4 v0 = ((const float4*)src)[0];
            float4 v1 = ((const float4*)src)[1];
            __half* p = g_W + ((size_t)mat << 16) + (size_t)c * 256 * 32 + (plane_off(r, t) >> 1);
            *(uint4*)p = pack8(v0, v1);
        }
    } else {
        const int w = (blockIdx.x - PREP_BLK1) * 8 + (tid >> 5);   // row 0..8191
        const int lane = tid & 31;
        const int b = w >> 10;
        const int rem = w & 1023;
        const int p = rem >> 5;
        const int q = rem & 31;
        const float4* x2v = (const float4*)pa.x2;
        const size_t base = ((size_t)(b * 64 + 2 * p) * 64 + 2 * q) * 64;
        const float4* s00 = x2v + base;
        const float4* s01 = x2v + base + 64;
        const float4* s10 = x2v + base + 4096;
        const float4* s11 = x2v + base + 4096 + 64;
        float4 a0 = s00[lane], a1 = s01[lane], a2 = s10[lane], a3 = s11[lane];
        float4 b0 = s00[lane + 32], b1 = s01[lane + 32], b2 = s10[lane + 32], b3 = s11[lane + 32];
        float4 v0 = make_float4(a0.x + a1.x + a2.x + a3.x, a0.y + a1.y + a2.y + a3.y,
                                a0.z + a1.z + a2.z + a3.z, a0.w + a1.w + a2.w + a3.w);
        float4 v1 = make_float4(b0.x + b1.x + b2.x + b3.x, b0.y + b1.y + b2.y + b3.y,
                                b0.z + b1.z + b2.z + b3.z, b0.w + b1.w + b2.w + b3.w);
        pb_store(w, lane, v0);
        pb_store(w, lane + 32, v1);
    }
}

// ---------------------------------------------------------------------------
// GEMM: BM=128, BN=128, BK=64 (two 32-k planes/chunk), 8 warps, 3-stage
// bulk-copy mbarrier ring (96KB smem, 2 CTAs/SM). K=512 jobs: chunks 4..7
// take A from fp32 gmem (A2f) via LDG+swizzled STS interleaved with compute.
// mode 0: plain; 1: scatter-up by F; 2: gather-add Cadd[coarse(m)].
// dep 0 none; 1 producer (signal g_done); 2 consumer (wait before epilogue).
// ---------------------------------------------------------------------------
struct TCJob {
    const __half *A1, *W1, *W2;
    const float* A2f;
    float* out;
    const float* Cadd;
    int aplane;   // bytes per A 32-k plane (= R*64)
    int tile_end, Hc, Wc, F, mode, dep;
};
struct TCJobs { TCJob j[5]; int njobs; int nprod; };

#define STG 32768                  // stage: A 16KB + B 16KB
#define SMEM_TOTAL (3 * STG)       // 98304

__global__ void __launch_bounds__(256, 2)
gemm_tc(TCJobs jobs) {
    extern __shared__ char smem[];
    __shared__ __align__(8) unsigned long long mbars[3];
    const uint32_t sb = smem_to_u32(smem);
    const uint32_t mb = smem_to_u32(mbars);
    const int tid = threadIdx.x;
    const int lid = tid & 31;
    const int wid = tid >> 5;
    const int wm = wid >> 2;       // 0..1
    const int wn = wid & 3;        // 0..3

    const int bt = blockIdx.x;
    int ji = 0;
#pragma unroll
    for (int t = 0; t < 4; ++t)
        if (t + 1 < jobs.njobs && bt >= jobs.j[t].tile_end) ji = t + 1;
    const TCJob jb = jobs.j[ji];
    const int local = bt - (ji == 0 ? 0 : jobs.j[ji - 1].tile_end);
    const int m0 = (local >> 1) * 128;
    const int n0 = (local & 1) * 128;

    const int nch = jb.W2 ? 8 : 4;   // BK=64 chunks

    float acc[4][4][4];
#pragma unroll
    for (int a = 0; a < 4; ++a)
#pragma unroll
        for (int b = 0; b < 4; ++b)
#pragma unroll
            for (int c = 0; c < 4; ++c) acc[a][b][c] = 0.f;

    if (tid == 0) {
#pragma unroll
        for (int s = 0; s < 3; ++s) MBARRIER_INIT(mb + 8 * s, 1);
    }
    __syncthreads();

    // issue chunk c into stage c%3 (B always bulk; A bulk only for c<4)
    auto issue = [&](int c) {
        const int s = c % 3;
        const uint32_t stg = sb + s * STG;
        const bool bulkA = (c < 4);
        MBARRIER_EXPECT_TX(mb + 8 * s, bulkA ? 32768u : 16384u);
        const char* wbase = (const char*)((c < 4) ? jb.W1 : jb.W2);
        const int cp = (c & 3) * 2;   // first 32-k plane of this chunk
        bulk_cp(stg + 16384, wbase + (size_t)cp * 16384 + n0 * 64, 8192, mb + 8 * s);
        bulk_cp(stg + 24576, wbase + (size_t)(cp + 1) * 16384 + n0 * 64, 8192, mb + 8 * s);
        if (bulkA) {
            const char* abase = (const char*)jb.A1;
            bulk_cp(stg, abase + (size_t)cp * jb.aplane + (size_t)m0 * 64, 8192, mb + 8 * s);
            bulk_cp(stg + 8192, abase + (size_t)(cp + 1) * jb.aplane + (size_t)m0 * 64, 8192,
                    mb + 8 * s);
        }
    };

    if (tid == 0) { issue(0); issue(1); }

    // A ldmatrix addresses (x4: 16 rows x 16 k)
    const int rA0 = wm * 64 + (lid & 15);
    const int hiA = lid >> 4;
    const uint32_t aBase = (rA0 >> 1) * 128;
    const int xvA = (rA0 >> 1) & 7;
    const int pbA = (rA0 & 1) << 2;
    const uint32_t soA0 = (uint32_t)(((pbA | hiA) ^ xvA) << 4);
    const uint32_t soA1 = (uint32_t)(((pbA | (2 + hiA)) ^ xvA) << 4);

    // B ldmatrix addresses (x4 covering TWO n8 tiles: lanes 16-31 -> rows +8)
    const int rB = wn * 32 + ((lid >> 4) & 1) * 8 + (lid & 7);
    const int hiB = (lid >> 3) & 1;
    const uint32_t bBase = (rB >> 1) * 128;
    const int xvB = (rB >> 1) & 7;
    const int pbB = (rB & 1) << 2;
    const uint32_t soB0 = (uint32_t)(((pbB | hiB) ^ xvB) << 4);
    const uint32_t soB1 = (uint32_t)(((pbB | (2 + hiB)) ^ xvB) << 4);

    // fp32 A path indices (thread covers one row, two 16B slots per plane)
    const int fr = tid >> 1;
    const int ft = (tid & 1) * 2;
    const uint32_t fsw0 = (uint32_t)((((((fr & 1) << 2) | ft) ^ ((fr >> 1) & 7)) << 4));
    const uint32_t fsw1 = (uint32_t)((((((fr & 1) << 2) | (ft + 1)) ^ ((fr >> 1) & 7)) << 4));
    const uint32_t frow = (uint32_t)((fr >> 1) * 128);

    float4 st[4];

#pragma unroll 1
    for (int c = 0; c < nch; ++c) {
        const int s = c % 3;
        MBARRIER_WAIT_PARITY(mb + 8 * s, (c / 3) & 1);

        const int c2 = c + 2;
        const bool ld2 = (c2 < nch) && (c2 >= 4);
        const uint32_t fstg = sb + (c2 % 3) * STG + frow;
        const float* fg = jb.A2f + (size_t)(m0 + fr) * 256 + (c2 & 3) * 64 + ft * 8;

        if (ld2) {   // plane 0 of chunk c2: k = [ft*8, ft*8+16)
            st[0] = ((const float4*)fg)[0];
            st[1] = ((const float4*)fg)[1];
            st[2] = ((const float4*)fg)[2];
            st[3] = ((const float4*)fg)[3];
        }

        const uint32_t sA0 = sb + s * STG;
        const uint32_t sB0 = sA0 + 16384;
#pragma unroll
        for (int h = 0; h < 2; ++h) {
            const uint32_t sA = sA0 + h * 8192;
            const uint32_t sB = sB0 + h * 8192;
#pragma unroll
            for (int ks = 0; ks < 2; ++ks) {
                uint32_t b[4][2];
                const uint32_t so = ks ? soB1 : soB0;
                {
                    uint32_t q[4];
                    ldsm4(q, sB + bBase + so);
                    b[0][0] = q[0]; b[0][1] = q[1];
                    b[1][0] = q[2]; b[1][1] = q[3];
                    ldsm4(q, sB + bBase + 1024 + so);
                    b[2][0] = q[0]; b[2][1] = q[1];
                    b[3][0] = q[2]; b[3][1] = q[3];
                }
                const uint32_t sak = ks ? soA1 : soA0;
#pragma unroll
                for (int mi = 0; mi < 4; ++mi) {
                    uint32_t a[4];
                    ldsm4(a, sA + aBase + mi * 1024 + sak);
#pragma unroll
                    for (int ni = 0; ni < 4; ++ni)
                        mma16816(acc[mi][ni], a, b[ni]);
                }
            }
            if (ld2) {
                if (h == 0) {
                    // store plane 0, then load plane 1 (k = 32 + ft*8 within
                    // the chunk -> float4 index 8..11 from fg)
                    sts128(fstg + fsw0, pack8(st[0], st[1]));
                    sts128(fstg + fsw1, pack8(st[2], st[3]));
                    st[0] = ((const float4*)fg)[8];
                    st[1] = ((const float4*)fg)[9];
                    st[2] = ((const float4*)fg)[10];
                    st[3] = ((const float4*)fg)[11];
                } else {
                    sts128(fstg + 8192 + fsw0, pack8(st[0], st[1]));
                    sts128(fstg + 8192 + fsw1, pack8(st[2], st[3]));
                }
            }
        }
        __syncthreads();
        if (c2 < nch && tid == 0) issue(c2);
    }

    // Consumers: wait for all C producers before the gather-add epilogue.
    if (jb.dep == 2) {
        if (tid == 0) {
            while (atomicAdd(&g_done, 0) < jobs.nprod) { }
        }
        __syncthreads();
    }

    // Epilogue. D frag: lane holds (row g, col 2tg), (row g+8) pairs.
    const int g = lid >> 2;
    const int tg = lid & 3;
#pragma unroll
    for (int mi = 0; mi < 4; ++mi) {
#pragma unroll
        for (int half = 0; half < 2; ++half) {
            const int rm = m0 + wm * 64 + mi * 16 + g + half * 8;
            if (jb.mode == 0) {
                float* dst = jb.out + (size_t)rm * 256;
#pragma unroll
                for (int ni = 0; ni < 4; ++ni) {
                    const int cn = n0 + wn * 32 + ni * 8 + tg * 2;
                    *(float2*)(dst + cn) = make_float2(acc[mi][ni][half * 2],
                                                       acc[mi][ni][half * 2 + 1]);
                }
            } else if (jb.mode == 1) {
                const int HW = jb.Hc * jb.Wc;
                const int b = rm / HW;
                const int rem = rm - b * HW;
                const int h = rem / jb.Wc;
                const int w = rem - h * jb.Wc;
                const int Wf = jb.Wc * jb.F;
                for (int dy = 0; dy < jb.F; ++dy)
                    for (int dx = 0; dx < jb.F; ++dx) {
                        size_t fm = (size_t)(b * jb.Hc * jb.F + h * jb.F + dy) * Wf
                                    + (w * jb.F + dx);
                        float* dst = jb.out + fm * 256;
#pragma unroll
                        for (int ni = 0; ni < 4; ++ni) {
                            const int cn = n0 + wn * 32 + ni * 8 + tg * 2;
                            *(float2*)(dst + cn) = make_float2(acc[mi][ni][half * 2],
                                                               acc[mi][ni][half * 2 + 1]);
                        }
                    }
            } else {
                const int Wf = jb.Wc * jb.F;
                const int HWf = jb.Hc * jb.F * Wf;
                const int b = rm / HWf;
                const int rem = rm - b * HWf;
                const int h = rem / Wf;
                const int w = rem - h * Wf;
                const int crow = (b * jb.Hc + h / jb.F) * jb.Wc + (w / jb.F);
                const float* csrc = jb.Cadd + (size_t)crow * 256;
                float* dst = jb.out + (size_t)rm * 256;
#pragma unroll
                for (int ni = 0; ni < 4; ++ni) {
                    const int cn = n0 + wn * 32 + ni * 8 + tg * 2;
                    float2 cv = *(const float2*)(csrc + cn);
                    *(float2*)(dst + cn) = make_float2(acc[mi][ni][half * 2] + cv.x,
                                                       acc[mi][ni][half * 2 + 1] + cv.y);
                }
            }
        }
    }

    // Producers: make C visible, then signal.
    if (jb.dep == 1) {
        __threadfence();
        __syncthreads();
        if (tid == 0) atomicAdd(&g_done, 1);
    }
}

// ---------------------------------------------------------------------------
// Launch
// ---------------------------------------------------------------------------
extern "C" void kernel_launch(void* const* d_in, const int* in_sizes, int n_in,
                              void* d_out, int out_size) {
    (void)n_in; (void)out_size;

    const float* x0 = (const float*)d_in[0];   // [8,16,16,256]
    const float* x1 = (const float*)d_in[1];   // [8,32,32,256]
    const float* x2 = (const float*)d_in[2];   // [8,64,64,256]

    // setup_inputs() builds the dict INTERLEAVED (qpeer_w0, kvpeer_w0, ...).
    const bool inter = (in_sizes[4] == 2 * 256 * 256);
    const float* kvpeer0 = (const float*)d_in[inter ? 4  : 6];
    const float* kvpeer1 = (const float*)d_in[inter ? 6  : 7];
    const float* kvpeer2 = (const float*)d_in[inter ? 8  : 8];
    const float* kvpar1  = (const float*)d_in[inter ? 10 : 11];
    const float* kvpar2  = (const float*)d_in[inter ? 12 : 12];
    const float* kvkid0  = (const float*)d_in[inter ? 14 : 15];
    const float* kvkid1  = (const float*)d_in[inter ? 16 : 16];

    __half *P0, *Pa, *Pb, *W;
    float *C0, *C1;
    cudaGetSymbolAddress((void**)&P0, g_P0);
    cudaGetSymbolAddress((void**)&Pa, g_Pa);
    cudaGetSymbolAddress((void**)&Pb, g_Pb);
    cudaGetSymbolAddress((void**)&W, g_W);
    cudaGetSymbolAddress((void**)&C0, g_C0);
    cudaGetSymbolAddress((void**)&C1, g_C1);

    float* out0 = (float*)d_out;                 // 8*16*16*256
    float* out1 = out0 + 8 * 16 * 16 * 256;      // 8*32*32*256
    float* out2 = out1 + 8 * 32 * 32 * 256;      // 8*64*64*256

    cudaFuncSetAttribute(gemm_tc, cudaFuncAttributeMaxDynamicSharedMemorySize, SMEM_TOTAL);

    // 1) prep (also resets g_done)
    PrepArgs pa;
    pa.x0 = x0; pa.x1 = x1; pa.x2 = x2;
    pa.w[0] = kvpeer0; pa.w[1] = kvpeer1; pa.w[2] = kvpeer2;
    pa.w[3] = kvpar1;  pa.w[4] = kvpar2;  pa.w[5] = kvkid0;  pa.w[6] = kvkid1;
    prep_kernel<<<PREP_BLOCKS, 256>>>(pa);

    __half* W0 = W;             // peer0
    __half* W1 = W + 65536;     // peer1
    __half* W2 = W + 131072;    // peer2
    __half* W3 = W + 196608;    // par1
    __half* W4 = W + 262144;    // par2
    __half* W5 = W + 327680;    // kid0
    __half* W6 = W + 393216;    // kid1

    // 2) single merged GEMM launch (producers first: blocks 0..33)
    TCJobs tj;
    tj.njobs = 5;
    tj.nprod = 34;
    //        A1  W1  W2      A2f  out   Cadd    aplane    end  Hc  Wc F  mode dep
    tj.j[0] = { P0, W0, nullptr, nullptr, C0,   nullptr, 128 * 64,  2,   0,  0, 0, 0, 1 };
    tj.j[1] = { Pa, W1, W3,      x0,      C1,   nullptr, 2048 * 64, 34,  0,  0, 0, 0, 1 };
    tj.j[2] = { Pb, W2, W4,      x1,      out2, nullptr, 8192 * 64, 162, 32, 32, 2, 1, 0 };
    tj.j[3] = { Pa, W5, nullptr, nullptr, out0, C0,      2048 * 64, 194, 4,  4,  4, 2, 2 };
    tj.j[4] = { Pb, W6, nullptr, nullptr, out1, C1,      8192 * 64, 322, 16, 16, 2, 2, 2 };
    gemm_tc<<<322, 256, SMEM_TOTAL>>>(tj);
}